// round 10
// baseline (speedup 1.0000x reference)
#include <cuda_runtime.h>
#include <cuda_bf16.h>

// 3D ROI pooling — coalesced row-segment version.
//   img:  (1, 256, 256, 256, 8) fp32, layout ((ix*256+iy)*256+iz)*8 + c
//   rois: (1, 64, 6) int32  [x, y, z, w, h, d]   (sizes in [8,64))
//   out:  (1, 64, 7, 7, 7, 8) fp32
//
// CTA per (roi, px): grid (7, 64), 128 threads.
// All z-accesses for a fixed (ix, iy) lie in the contiguous segment
// img[ix][iy][z .. z+d-1] (<= 63 voxels = <=2KB). Load whole segments
// COALESCED (float4 per lane, sequential) into smem, interpolate from smem.
// Two passes over the x-corner (jx0 rows, then jx1 rows) keep smem at
// 14 rows x 128 float4 = 28KB static.

#define NUM_ROIS 64
#define PS 7
#define CELLS (PS * PS * PS)     // 343
#define DIM 256
#define MAXL 128                 // max float4s per row segment: 64 voxels * 2

__global__ void __launch_bounds__(128) roi_pool3d_kernel(
    const float* __restrict__ img,
    const int* __restrict__ rois,
    float* __restrict__ out)
{
    __shared__ float4 srow[14][MAXL];     // 28 KB

    const int px  = blockIdx.x;           // 0..6
    const int roi = blockIdx.y;           // 0..63
    const int tid = threadIdx.x;          // 0..127
    const int wid = tid >> 5;
    const int lane = tid & 31;

    // ROI row: 6 ints, 8B-aligned -> three int2 loads
    const int2* r2p = (const int2*)(rois + roi * 6);
    int2 rxy = __ldg(r2p + 0);
    int2 rzw = __ldg(r2p + 1);
    int2 rhd = __ldg(r2p + 2);
    int x = rxy.x, y = rxy.y, z = rzw.x;
    int w = rzw.y, h = rhd.x, d = rhd.y;

    // x-axis coords for this px (reference fp32 arithmetic)
    float sx = (float)px * ((float)w / (float)PS);
    int ix0 = (int)floorf(sx);
    float fx = sx - (float)ix0;
    int ix1 = min(ix0 + 1, w - 1);
    ix0 = min(ix0, w - 1);
    int jx0 = x + ix0, jx1 = x + ix1;

    const int L = d * 2;                  // float4s per row segment (voxels [0,d))
    const float4* __restrict__ base = (const float4*)img;

    // ---- helper lambda-ish: y row index for slot b in [0,14) ----
    // slot b<7  -> y-corner0 of py=b ;  b>=7 -> y-corner1 of py=b-7
    auto jy_of = [&](int b) {
        int pyb = (b < 7) ? b : b - 7;
        float sy = (float)pyb * ((float)h / (float)PS);
        int i0 = (int)floorf(sy);
        int idx = (b < 7) ? min(i0, h - 1) : min(i0 + 1, h - 1);
        return y + idx;
    };

    // ---- per-thread compute setup (valid for t < 98) ----
    int half = tid & 1;
    int cell = tid >> 1;                  // 0..48 when tid<98
    int py = cell / 7;
    int pz = cell - py * 7;
    bool active = (tid < 98);

    float fy = 0.f, fz = 0.f;
    int iz0 = 0, iz1 = 0;
    if (active) {
        float sy = (float)py * ((float)h / (float)PS);
        int i0y = (int)floorf(sy);
        fy = sy - (float)i0y;

        float sz = (float)pz * ((float)d / (float)PS);
        iz0 = (int)floorf(sz);
        fz = sz - (float)iz0;
        iz1 = min(iz0 + 1, d - 1);
        iz0 = min(iz0, d - 1);
    }
    float gy = 1.0f - fy, gz = 1.0f - fz, gx = 1.0f - fx;

    float4 acc = make_float4(0.f, 0.f, 0.f, 0.f);

    #pragma unroll
    for (int xc = 0; xc < 2; xc++) {
        int jx = xc ? jx1 : jx0;

        // ---- load 14 row segments, coalesced (warp per row, rr) ----
        for (int b = wid; b < 14; b += 4) {
            int jy = jy_of(b);
            const float4* src = base + (size_t)((jx * DIM + jy) * DIM + z) * 2;
            for (int i = lane; i < L; i += 32)
                srow[b][i] = src[i];
        }
        __syncthreads();

        // ---- interpolate (y,z) bilinear at this x-corner ----
        if (active) {
            float4 v00 = srow[py][iz0 * 2 + half];
            float4 v01 = srow[py][iz1 * 2 + half];
            float4 v10 = srow[7 + py][iz0 * 2 + half];
            float4 v11 = srow[7 + py][iz1 * 2 + half];

            float wxc = xc ? fx : gx;
            float4 c;
            c.x = ((v00.x * gz + v01.x * fz) * gy + (v10.x * gz + v11.x * fz) * fy) * wxc;
            c.y = ((v00.y * gz + v01.y * fz) * gy + (v10.y * gz + v11.y * fz) * fy) * wxc;
            c.z = ((v00.z * gz + v01.z * fz) * gy + (v10.z * gz + v11.z * fz) * fy) * wxc;
            c.w = ((v00.w * gz + v01.w * fz) * gy + (v10.w * gz + v11.w * fz) * fy) * wxc;
            acc.x += c.x;  acc.y += c.y;  acc.z += c.z;  acc.w += c.w;
        }
        if (xc == 0) __syncthreads();     // protect smem before overwrite
    }

    if (active) {
        // out index: (roi*343 + ((px*7+py)*7+pz)) * 2 + half
        int ocell = (px * PS + py) * PS + pz;
        ((float4*)out)[(size_t)(roi * CELLS + ocell) * 2 + half] = acc;
    }
}

extern "C" void kernel_launch(void* const* d_in, const int* in_sizes, int n_in,
                              void* d_out, int out_size)
{
    const float* img  = (const float*)d_in[0];
    const int*   rois = (const int*)d_in[1];
    float*       out  = (float*)d_out;

    dim3 grid(PS, NUM_ROIS);   // (7, 64) = 448 CTAs
    roi_pool3d_kernel<<<grid, 128>>>(img, rois, out);
}

// round 13
// speedup vs baseline: 1.6329x; 1.6329x over previous
#include <cuda_runtime.h>
#include <cuda_bf16.h>

// 3D ROI pooling — R1 structure + single-wave + divide-free decode.
//   img:  (1, 256, 256, 256, 8) fp32, layout ((ix*256+iy)*256+iz)*8 + c
//   rois: (1, 64, 6) int32  [x, y, z, w, h, d]
//   out:  (1, 64, 7, 7, 7, 8) fp32
//
// One thread per (cell, channel-half), index space padded to powers of 2:
//   tid = roi<<10 | px<<7 | py<<4 | pz<<1 | half     (65536 threads)
// Grid = 128 CTAs x 512 threads -> exactly one wave, one CTA per SM.
// Decode is pure bit ops; each active thread issues 8 independent LDG.128.

#define NUM_ROIS 64
#define PS 7
#define CELLS (PS * PS * PS)            // 343
#define DIM 256

__global__ void __launch_bounds__(512) roi_pool3d_kernel(
    const float* __restrict__ img,
    const int* __restrict__ rois,
    float* __restrict__ out)
{
    int tid = blockIdx.x * 512 + threadIdx.x;   // 0 .. 65535

    int half = tid & 1;
    int pz   = (tid >> 1) & 7;
    int py   = (tid >> 4) & 7;
    int px   = (tid >> 7) & 7;
    int roi  = tid >> 10;

    if (px == 7 || py == 7 || pz == 7) return;   // padding lanes

    // roi row: 6 ints at 24B offset, 8B aligned -> three int2 loads
    const int2* r2p = (const int2*)(rois + roi * 6);
    int2 rxy = __ldg(r2p + 0);    // x, y
    int2 rzw = __ldg(r2p + 1);    // z, w
    int2 rhd = __ldg(r2p + 2);    // h, d
    int x = rxy.x, y = rxy.y, z = rzw.x;
    int w = rzw.y, h = rhd.x, d = rhd.y;

    // --- axis coords (reference fp32 arithmetic) ---
    float sx = (float)px * ((float)w / (float)PS);
    int ix0 = (int)floorf(sx);
    float fx = sx - (float)ix0;
    int ix1 = min(ix0 + 1, w - 1);
    ix0 = min(ix0, w - 1);

    float sy = (float)py * ((float)h / (float)PS);
    int iy0 = (int)floorf(sy);
    float fy = sy - (float)iy0;
    int iy1 = min(iy0 + 1, h - 1);
    iy0 = min(iy0, h - 1);

    float sz = (float)pz * ((float)d / (float)PS);
    int iz0 = (int)floorf(sz);
    float fz = sz - (float)iz0;
    int iz1 = min(iz0 + 1, d - 1);
    iz0 = min(iz0, d - 1);

    int jx0 = x + ix0, jx1 = x + ix1;
    int jy0 = y + iy0, jy1 = y + iy1;
    int jz0 = z + iz0, jz1 = z + iz1;

    // float4 index: ((ix*256+iy)*256+iz)*2 + half
    const float4* __restrict__ base = (const float4*)img;
    int row00 = (jx0 * DIM + jy0) * DIM;
    int row01 = (jx0 * DIM + jy1) * DIM;
    int row10 = (jx1 * DIM + jy0) * DIM;
    int row11 = (jx1 * DIM + jy1) * DIM;

    size_t b000 = (size_t)(row00 + jz0) * 2 + half;
    size_t b001 = (size_t)(row00 + jz1) * 2 + half;
    size_t b010 = (size_t)(row01 + jz0) * 2 + half;
    size_t b011 = (size_t)(row01 + jz1) * 2 + half;
    size_t b100 = (size_t)(row10 + jz0) * 2 + half;
    size_t b101 = (size_t)(row10 + jz1) * 2 + half;
    size_t b110 = (size_t)(row11 + jz0) * 2 + half;
    size_t b111 = (size_t)(row11 + jz1) * 2 + half;

    // 8 independent LDG.128 (MLP = 8)
    float4 v000 = base[b000];
    float4 v001 = base[b001];
    float4 v010 = base[b010];
    float4 v011 = base[b011];
    float4 v100 = base[b100];
    float4 v101 = base[b101];
    float4 v110 = base[b110];
    float4 v111 = base[b111];

    float gz = 1.0f - fz, gy = 1.0f - fy, gx = 1.0f - fx;

    float4 o;
    {
        float c00, c01, c10, c11, c0, c1;
        c00 = v000.x * gz + v001.x * fz;
        c01 = v010.x * gz + v011.x * fz;
        c10 = v100.x * gz + v101.x * fz;
        c11 = v110.x * gz + v111.x * fz;
        c0 = c00 * gy + c01 * fy;
        c1 = c10 * gy + c11 * fy;
        o.x = c0 * gx + c1 * fx;

        c00 = v000.y * gz + v001.y * fz;
        c01 = v010.y * gz + v011.y * fz;
        c10 = v100.y * gz + v101.y * fz;
        c11 = v110.y * gz + v111.y * fz;
        c0 = c00 * gy + c01 * fy;
        c1 = c10 * gy + c11 * fy;
        o.y = c0 * gx + c1 * fx;

        c00 = v000.z * gz + v001.z * fz;
        c01 = v010.z * gz + v011.z * fz;
        c10 = v100.z * gz + v101.z * fz;
        c11 = v110.z * gz + v111.z * fz;
        c0 = c00 * gy + c01 * fy;
        c1 = c10 * gy + c11 * fy;
        o.z = c0 * gx + c1 * fx;

        c00 = v000.w * gz + v001.w * fz;
        c01 = v010.w * gz + v011.w * fz;
        c10 = v100.w * gz + v101.w * fz;
        c11 = v110.w * gz + v111.w * fz;
        c0 = c00 * gy + c01 * fy;
        c1 = c10 * gy + c11 * fy;
        o.w = c0 * gx + c1 * fx;
    }

    // output vec index = (roi*343 + ((px*7+py)*7+pz))*2 + half
    int cell = (px * PS + py) * PS + pz;
    ((float4*)out)[(size_t)(roi * CELLS + cell) * 2 + half] = o;
}

extern "C" void kernel_launch(void* const* d_in, const int* in_sizes, int n_in,
                              void* d_out, int out_size)
{
    const float* img  = (const float*)d_in[0];
    const int*   rois = (const int*)d_in[1];
    float*       out  = (float*)d_out;

    // 64 rois * 1024 padded slots = 65536 threads = 128 CTAs x 512 (single wave)
    roi_pool3d_kernel<<<128, 512>>>(img, rois, out);
}